// round 8
// baseline (speedup 1.0000x reference)
#include <cuda_runtime.h>

// LocallyConnected1d: out[b,o,l] = sum_{c,k} x[b,c,l+k]*w[o,c,l,k] + bias[o,l]
// B=32, Cin=128, Cout=128, L=2048, K=3, S=1, W=2050, fp32.
//
// f32x2 packed-FMA (b-pairs). 5-buffer cp.async pipeline, prefetch dist 3.
// Warp-structured coalesced fills (R7). NEW: x smem reads use shuffle-based
// k-reuse — 2 LDS.64 + 2 SHFL + 1 SEL per (ci,bp) instead of 3 LDS.64,
// cutting x crossbar bytes 33% (the binding pipe per ncu).

#define CIN     128
#define COUT    128
#define LOUT    2048
#define KW      3
#define WIN     2050

#define L_TILE  32
#define O_TILE  16
#define CC      2                     // Cin per pipeline stage
#define NST     (CIN / CC)            // 64 stages
#define NBUF    5
#define NTHREADS 256

#define XPAD    34                    // u64 (float2) per (ci,bp) row
#define STAGE_X (CC * 16 * XPAD * 2)  // 2176 floats
#define STAGE_W (CC * O_TILE * 96)    // 3072 floats
#define STAGE_F (STAGE_X + STAGE_W)   // 5248 floats
#define STAGE_BYTES (STAGE_F * 4)     // 20992 B
#define SMEM_BYTES (NBUF * STAGE_BYTES)  // 104960 B -> 2 blocks/SM

typedef unsigned long long u64;

static __device__ __forceinline__ u64 pack_dup(float a) {
    u64 r; asm("mov.b64 %0, {%1, %1};" : "=l"(r) : "f"(a)); return r;
}
static __device__ __forceinline__ void unpack2(u64 v, float& a, float& b) {
    asm("mov.b64 {%0, %1}, %2;" : "=f"(a), "=f"(b) : "l"(v));
}
static __device__ __forceinline__ void ffma2(u64& d, u64 a, u64 b) {
    asm("fma.rn.f32x2 %0, %1, %2, %0;" : "+l"(d) : "l"(a), "l"(b));
}
static __device__ __forceinline__ unsigned smem_u32(const void* p) {
    unsigned r;
    asm("{ .reg .u64 t; cvta.to.shared.u64 t, %1; cvt.u32.u64 %0, t; }"
        : "=r"(r) : "l"(p));
    return r;
}
static __device__ __forceinline__ void cpa4(unsigned d, const float* s) {
    asm volatile("cp.async.ca.shared.global [%0], [%1], 4;" :: "r"(d), "l"(s));
}
static __device__ __forceinline__ void cpa16(unsigned d, const float* s) {
    asm volatile("cp.async.cg.shared.global [%0], [%1], 16;" :: "r"(d), "l"(s));
}
#define CP_COMMIT() asm volatile("cp.async.commit_group;" ::: "memory")
#define CP_WAIT2()  asm volatile("cp.async.wait_group 2;" ::: "memory")
#define CP_WAIT1()  asm volatile("cp.async.wait_group 1;" ::: "memory")
#define CP_WAIT0()  asm volatile("cp.async.wait_group 0;" ::: "memory")

__global__ void __launch_bounds__(NTHREADS, 2)
lc1d_kernel(const float* __restrict__ x,
            const float* __restrict__ wgt,
            const float* __restrict__ bias,
            float* __restrict__ out)
{
    extern __shared__ float smem[];
    const unsigned sb = smem_u32(smem);

    const int tid  = threadIdx.x;
    const int lane = tid & 31;            // local l index (compute)
    const int warp = tid >> 5;
    const int bp0  = (warp & 3) * 4;      // b-pair group start (compute)
    const int og   = (warp >> 2) * 8;     // o group start (compute)
    const int l0   = blockIdx.x * L_TILE;
    const int o0   = blockIdx.y * O_TILE;

    // ================= fill state (warp-specialized, hoisted; R7) =========
    // X warps (0-3): main sweep w=0..31 coalesced + 1 tail element.
    // W warps (4-7): lanes 0..23 sweep 96-float runs as float4.
    const bool is_x = (warp < 4);
    const float* srcA;
    const float* srcB = nullptr;
    unsigned dstA, dstB = 0;
    long cadv;
    if (is_x) {
        const int ci0 = warp >> 1;
        const int b0f = (warp & 1) * 16;
        srcA = x + ((long)(b0f * CIN + ci0)) * WIN + l0 + lane;
        dstA = (unsigned)((ci0 * 16 + b0f / 2) * 68 + lane * 2);
        srcB = x + ((long)((b0f + (lane >> 1)) * CIN + ci0)) * WIN
                 + l0 + 32 + (lane & 1);
        dstB = (unsigned)(((ci0 * 16 + b0f / 2 + (lane >> 2)) * 34
                           + 32 + (lane & 1)) * 2 + ((lane >> 1) & 1));
        cadv = (long)CC * WIN;
    } else {
        const int ww  = warp - 4;
        const int ci0 = ww >> 1;
        const int oi0 = (ww & 1) * 8;
        srcA = wgt + ((long)((o0 + oi0) * CIN + ci0)) * (LOUT * KW)
                   + l0 * KW + lane * 4;
        dstA = (unsigned)(STAGE_X + (ci0 * 16 + oi0) * 96 + lane * 4);
        cadv = (long)CC * LOUT * KW;
    }

    u64 acc[4][8];
    #pragma unroll
    for (int p = 0; p < 4; p++)
        #pragma unroll
        for (int o = 0; o < 8; o++) acc[p][o] = 0ull;

    #define ISSUE(buf) do {                                                 \
        unsigned d0_ = sb + (unsigned)(buf) * STAGE_BYTES + dstA * 4u;      \
        if (is_x) {                                                         \
            _Pragma("unroll")                                               \
            for (int i_ = 0; i_ < 16; i_++)                                 \
                cpa4(d0_ + (unsigned)(((i_ >> 1) * 68 + (i_ & 1)) * 4),     \
                     srcA + (long)i_ * (CIN * WIN));                        \
            cpa4(sb + (unsigned)(buf) * STAGE_BYTES + dstB * 4u, srcB);     \
            srcB += cadv;                                                   \
        } else if (lane < 24) {                                             \
            _Pragma("unroll")                                               \
            for (int i_ = 0; i_ < 8; i_++)                                  \
                cpa16(d0_ + (unsigned)(i_ * 96 * 4),                        \
                      srcA + (long)i_ * (CIN * LOUT * KW));                 \
        }                                                                   \
        srcA += cadv;                                                       \
    } while (0)

    // prologue: prefetch stages 0..2
    ISSUE(0); CP_COMMIT();
    ISSUE(1); CP_COMMIT();
    ISSUE(2); CP_COMMIT();

    int bC = 0;                            // s % NBUF (compute buffer)
    int bI = 3;                            // (s+3) % NBUF (issue buffer)

    #pragma unroll 1
    for (int s = 0; s < NST; s++) {
        if (s < NST - 2)      { CP_WAIT2(); }
        else if (s == NST - 2){ CP_WAIT1(); }
        else                  { CP_WAIT0(); }
        __syncthreads();                    // stage s visible block-wide

        if (s + 3 < NST) {                  // prefetch s+3 (distance 3)
            ISSUE(bI);
            CP_COMMIT();
        }

        const float* Xb = smem + bC * STAGE_F;
        const float* Wb = Xb + STAGE_X;
        const u64* Xu = reinterpret_cast<const u64*>(Xb);

        #pragma unroll
        for (int ci = 0; ci < CC; ci++) {
            // x via shuffle k-reuse: per bp, 2 LDS.64 cover w=lane, lane+2;
            // w=lane+1 comes from neighbor lanes (both shfl directions give
            // it; each is invalid at one end lane -> one SEL repairs).
            u64 px[4][3];
            #pragma unroll
            for (int p = 0; p < 4; p++) {
                const u64* row = Xu + (ci * 16 + bp0 + p) * XPAD;
                u64 v0 = row[lane];           // w = lane
                u64 v2 = row[lane + 2];       // w = lane+2 (<= 33, in-row)
                u64 dn = __shfl_down_sync(0xffffffffu, v0, 1); // w=lane+1, bad@31
                u64 up = __shfl_up_sync(0xffffffffu, v2, 1);   // w=lane+1, bad@0
                px[p][0] = v0;
                px[p][1] = (lane == 31) ? up : dn;
                px[p][2] = v2;
            }
            #pragma unroll
            for (int k = 0; k < KW; k++) {
                // w: stride-3 lane addressing, coprime with 32 banks
                const float* wp = Wb + (ci * O_TILE + og) * 96 + lane * KW + k;
                #pragma unroll
                for (int oi = 0; oi < 8; oi++) {
                    u64 wv = pack_dup(wp[oi * 96]);
                    ffma2(acc[0][oi], px[0][k], wv);
                    ffma2(acc[1][oi], px[1][k], wv);
                    ffma2(acc[2][oi], px[2][k], wv);
                    ffma2(acc[3][oi], px[3][k], wv);
                }
            }
        }

        if (++bC == NBUF) bC = 0;
        if (++bI == NBUF) bI = 0;
    }

    // epilogue: bias + coalesced stores (l-contiguous)
    const int b0 = (warp & 3) * 8;
    #pragma unroll
    for (int oi = 0; oi < 8; oi++) {
        int o = o0 + og + oi;
        float bv = bias[o * LOUT + l0 + lane];
        #pragma unroll
        for (int p = 0; p < 4; p++) {
            float f0, f1;
            unpack2(acc[p][oi], f0, f1);
            int b = b0 + 2 * p;
            out[(b * COUT + o) * LOUT + l0 + lane]       = f0 + bv;
            out[((b + 1) * COUT + o) * LOUT + l0 + lane] = f1 + bv;
        }
    }
}

extern "C" void kernel_launch(void* const* d_in, const int* in_sizes, int n_in,
                              void* d_out, int out_size)
{
    const float* x    = (const float*)d_in[0];
    const float* wgt  = (const float*)d_in[1];
    const float* bias = (const float*)d_in[2];
    float* out        = (float*)d_out;

    cudaFuncSetAttribute(lc1d_kernel,
                         cudaFuncAttributeMaxDynamicSharedMemorySize, SMEM_BYTES);

    dim3 grid(LOUT / L_TILE, COUT / O_TILE);   // (64, 8) = 512 blocks
    lc1d_kernel<<<grid, NTHREADS, SMEM_BYTES>>>(x, wgt, bias, out);
}

// round 9
// speedup vs baseline: 1.0659x; 1.0659x over previous
#include <cuda_runtime.h>

// LocallyConnected1d: out[b,o,l] = sum_{c,k} x[b,c,l+k]*w[o,c,l,k] + bias[o,l]
// B=32, Cin=128, Cout=128, L=2048, K=3, S=1, W=2050, fp32.
//
// R7-proven core: f32x2 packed-FMA (b-pairs), 4x LDS.64 x-reads, stride-3
// w-reads, warp-structured coalesced hoisted fills.
// R9: NBUF=5 dist-3 pipeline, fill issued BEFORE the wait (overlaps barrier
// stall; buffer (s+3)%5 provably free), o-major grid raster for x L2 reuse.

#define CIN     128
#define COUT    128
#define LOUT    2048
#define KW      3
#define WIN     2050

#define L_TILE  32
#define O_TILE  16
#define CC      2                     // Cin per pipeline stage
#define NST     (CIN / CC)            // 64 stages
#define NBUF    5
#define NTHREADS 256

#define XPAD    34                    // u64 (float2) per (ci,bp) row
#define STAGE_X (CC * 16 * XPAD * 2)  // 2176 floats
#define STAGE_W (CC * O_TILE * 96)    // 3072 floats
#define STAGE_F (STAGE_X + STAGE_W)   // 5248 floats
#define STAGE_BYTES (STAGE_F * 4)     // 20992 B
#define SMEM_BYTES (NBUF * STAGE_BYTES)  // 104960 B -> 2 blocks/SM

typedef unsigned long long u64;

static __device__ __forceinline__ u64 pack_dup(float a) {
    u64 r; asm("mov.b64 %0, {%1, %1};" : "=l"(r) : "f"(a)); return r;
}
static __device__ __forceinline__ void unpack2(u64 v, float& a, float& b) {
    asm("mov.b64 {%0, %1}, %2;" : "=f"(a), "=f"(b) : "l"(v));
}
static __device__ __forceinline__ void ffma2(u64& d, u64 a, u64 b) {
    asm("fma.rn.f32x2 %0, %1, %2, %0;" : "+l"(d) : "l"(a), "l"(b));
}
static __device__ __forceinline__ unsigned smem_u32(const void* p) {
    unsigned r;
    asm("{ .reg .u64 t; cvta.to.shared.u64 t, %1; cvt.u32.u64 %0, t; }"
        : "=r"(r) : "l"(p));
    return r;
}
static __device__ __forceinline__ void cpa4(unsigned d, const float* s) {
    asm volatile("cp.async.ca.shared.global [%0], [%1], 4;" :: "r"(d), "l"(s));
}
static __device__ __forceinline__ void cpa16(unsigned d, const float* s) {
    asm volatile("cp.async.cg.shared.global [%0], [%1], 16;" :: "r"(d), "l"(s));
}
#define CP_COMMIT() asm volatile("cp.async.commit_group;" ::: "memory")
#define CP_WAIT3()  asm volatile("cp.async.wait_group 3;" ::: "memory")
#define CP_WAIT0()  asm volatile("cp.async.wait_group 0;" ::: "memory")

__global__ void __launch_bounds__(NTHREADS, 2)
lc1d_kernel(const float* __restrict__ x,
            const float* __restrict__ wgt,
            const float* __restrict__ bias,
            float* __restrict__ out)
{
    extern __shared__ float smem[];
    const unsigned sb = smem_u32(smem);

    const int tid  = threadIdx.x;
    const int lane = tid & 31;            // local l index (compute)
    const int warp = tid >> 5;
    const int bp0  = (warp & 3) * 4;      // b-pair group start (compute)
    const int og   = (warp >> 2) * 8;     // o group start (compute)
    // o-major raster: blockIdx.x = o tile (fast) -> 8 o-blocks sharing an
    // x-tile are co-resident -> x hits L2
    const int o0   = blockIdx.x * O_TILE;
    const int l0   = blockIdx.y * L_TILE;

    // ================= fill state (warp-specialized, hoisted; R7) =========
    // X warps (0-3): main sweep w=0..31 coalesced + 1 tail element.
    // W warps (4-7): lanes 0..23 sweep 96-float runs as float4.
    const bool is_x = (warp < 4);
    const float* srcA;
    const float* srcB = nullptr;
    unsigned dstA, dstB = 0;
    long cadv;
    if (is_x) {
        const int ci0 = warp >> 1;
        const int b0f = (warp & 1) * 16;
        srcA = x + ((long)(b0f * CIN + ci0)) * WIN + l0 + lane;
        dstA = (unsigned)((ci0 * 16 + b0f / 2) * 68 + lane * 2);
        srcB = x + ((long)((b0f + (lane >> 1)) * CIN + ci0)) * WIN
                 + l0 + 32 + (lane & 1);
        dstB = (unsigned)(((ci0 * 16 + b0f / 2 + (lane >> 2)) * 34
                           + 32 + (lane & 1)) * 2 + ((lane >> 1) & 1));
        cadv = (long)CC * WIN;
    } else {
        const int ww  = warp - 4;
        const int ci0 = ww >> 1;
        const int oi0 = (ww & 1) * 8;
        srcA = wgt + ((long)((o0 + oi0) * CIN + ci0)) * (LOUT * KW)
                   + l0 * KW + lane * 4;
        dstA = (unsigned)(STAGE_X + (ci0 * 16 + oi0) * 96 + lane * 4);
        cadv = (long)CC * LOUT * KW;
    }

    u64 acc[4][8];
    #pragma unroll
    for (int p = 0; p < 4; p++)
        #pragma unroll
        for (int o = 0; o < 8; o++) acc[p][o] = 0ull;

    #define ISSUE(buf) do {                                                 \
        unsigned d0_ = sb + (unsigned)(buf) * STAGE_BYTES + dstA * 4u;      \
        if (is_x) {                                                         \
            _Pragma("unroll")                                               \
            for (int i_ = 0; i_ < 16; i_++)                                 \
                cpa4(d0_ + (unsigned)(((i_ >> 1) * 68 + (i_ & 1)) * 4),     \
                     srcA + (long)i_ * (CIN * WIN));                        \
            cpa4(sb + (unsigned)(buf) * STAGE_BYTES + dstB * 4u, srcB);     \
            srcB += cadv;                                                   \
        } else if (lane < 24) {                                             \
            _Pragma("unroll")                                               \
            for (int i_ = 0; i_ < 8; i_++)                                  \
                cpa16(d0_ + (unsigned)(i_ * 96 * 4),                        \
                      srcA + (long)i_ * (CIN * LOUT * KW));                 \
        }                                                                   \
        srcA += cadv;                                                       \
    } while (0)

    // prologue: prefetch stages 0..2
    ISSUE(0); CP_COMMIT();
    ISSUE(1); CP_COMMIT();
    ISSUE(2); CP_COMMIT();

    int bC = 0;                            // s % NBUF (compute buffer)
    int bI = 3;                            // (s+3) % NBUF (issue buffer)

    #pragma unroll 1
    for (int s = 0; s < NST; s++) {
        // Issue fill for s+3 FIRST: buffer bI == (s-2)%NBUF was consumed as
        // stage s-2 by every warp before barrier(s-1), which every warp here
        // has passed. The cp.asyncs then overlap the wait+barrier stall.
        if (s + 3 < NST) {
            ISSUE(bI);
            CP_COMMIT();
            CP_WAIT3();                    // stage s's group done (3 pending)
        } else {
            CP_WAIT0();
        }
        __syncthreads();                   // stage s visible block-wide

        const float* Xb = smem + bC * STAGE_F;
        const float* Wb = Xb + STAGE_X;
        const u64* Xu = reinterpret_cast<const u64*>(Xb);

        #pragma unroll
        for (int ci = 0; ci < CC; ci++) {
            #pragma unroll
            for (int k = 0; k < KW; k++) {
                const u64* xp = Xu + (ci * 16 + bp0) * XPAD + lane + k;
                const u64 px0 = xp[0];
                const u64 px1 = xp[XPAD];
                const u64 px2 = xp[2 * XPAD];
                const u64 px3 = xp[3 * XPAD];
                // stride-3 lane addressing: coprime with 32 banks
                const float* wp = Wb + (ci * O_TILE + og) * 96 + lane * KW + k;
                #pragma unroll
                for (int oi = 0; oi < 8; oi++) {
                    u64 wv = pack_dup(wp[oi * 96]);
                    ffma2(acc[0][oi], px0, wv);
                    ffma2(acc[1][oi], px1, wv);
                    ffma2(acc[2][oi], px2, wv);
                    ffma2(acc[3][oi], px3, wv);
                }
            }
        }

        if (++bC == NBUF) bC = 0;
        if (++bI == NBUF) bI = 0;
    }

    // epilogue: bias + coalesced stores (l-contiguous)
    const int b0 = (warp & 3) * 8;
    #pragma unroll
    for (int oi = 0; oi < 8; oi++) {
        int o = o0 + og + oi;
        float bv = bias[o * LOUT + l0 + lane];
        #pragma unroll
        for (int p = 0; p < 4; p++) {
            float f0, f1;
            unpack2(acc[p][oi], f0, f1);
            int b = b0 + 2 * p;
            out[(b * COUT + o) * LOUT + l0 + lane]       = f0 + bv;
            out[((b + 1) * COUT + o) * LOUT + l0 + lane] = f1 + bv;
        }
    }
}

extern "C" void kernel_launch(void* const* d_in, const int* in_sizes, int n_in,
                              void* d_out, int out_size)
{
    const float* x    = (const float*)d_in[0];
    const float* wgt  = (const float*)d_in[1];
    const float* bias = (const float*)d_in[2];
    float* out        = (float*)d_out;

    cudaFuncSetAttribute(lc1d_kernel,
                         cudaFuncAttributeMaxDynamicSharedMemorySize, SMEM_BYTES);

    dim3 grid(COUT / O_TILE, LOUT / L_TILE);   // (8, 64): o fastest
    lc1d_kernel<<<grid, NTHREADS, SMEM_BYTES>>>(x, wgt, bias, out);
}

// round 10
// speedup vs baseline: 1.0992x; 1.0312x over previous
#include <cuda_runtime.h>

// LocallyConnected1d: out[b,o,l] = sum_{c,k} x[b,c,l+k]*w[o,c,l,k] + bias[o,l]
// B=32, Cin=128, Cout=128, L=2048, K=3, S=1, W=2050, fp32.
//
// R7-proven core: f32x2 packed-FMA (b-pairs), 4x LDS.64 x-reads, stride-3
// w-reads, warp-specialized hoisted coalesced cp.async fills.
// R10: CC=4 / NBUF=2 / dist-1 -> HALF the sync points (32 barriers+waits);
// fill(s+1) issued post-barrier overlaps the ~3000-cyc compute(s), far
// above DRAM latency, so wait_group 0 never blocks. o-major raster kept
// (x served from L2 across the 8 co-resident o-blocks; measured -80MB DRAM).

#define CIN     128
#define COUT    128
#define LOUT    2048
#define KW      3
#define WIN     2050

#define L_TILE  32
#define O_TILE  16
#define CC      4                     // Cin per pipeline stage
#define NST     (CIN / CC)            // 32 stages
#define NTHREADS 256

#define XPAD    34                    // u64 (float2) per (ci,bp) row
#define STAGE_X (CC * 16 * XPAD * 2)  // 4352 floats
#define STAGE_W (CC * O_TILE * 96)    // 6144 floats
#define STAGE_F (STAGE_X + STAGE_W)   // 10496 floats
#define STAGE_BYTES (STAGE_F * 4)     // 41984 B
#define SMEM_BYTES (2 * STAGE_BYTES)  // 83968 B -> 2 blocks/SM

typedef unsigned long long u64;

static __device__ __forceinline__ u64 pack_dup(float a) {
    u64 r; asm("mov.b64 %0, {%1, %1};" : "=l"(r) : "f"(a)); return r;
}
static __device__ __forceinline__ void unpack2(u64 v, float& a, float& b) {
    asm("mov.b64 {%0, %1}, %2;" : "=f"(a), "=f"(b) : "l"(v));
}
static __device__ __forceinline__ void ffma2(u64& d, u64 a, u64 b) {
    asm("fma.rn.f32x2 %0, %1, %2, %0;" : "+l"(d) : "l"(a), "l"(b));
}
static __device__ __forceinline__ unsigned smem_u32(const void* p) {
    unsigned r;
    asm("{ .reg .u64 t; cvta.to.shared.u64 t, %1; cvt.u32.u64 %0, t; }"
        : "=r"(r) : "l"(p));
    return r;
}
static __device__ __forceinline__ void cpa4(unsigned d, const float* s) {
    asm volatile("cp.async.ca.shared.global [%0], [%1], 4;" :: "r"(d), "l"(s));
}
static __device__ __forceinline__ void cpa16(unsigned d, const float* s) {
    asm volatile("cp.async.cg.shared.global [%0], [%1], 16;" :: "r"(d), "l"(s));
}
#define CP_COMMIT() asm volatile("cp.async.commit_group;" ::: "memory")
#define CP_WAIT0()  asm volatile("cp.async.wait_group 0;" ::: "memory")

__global__ void __launch_bounds__(NTHREADS, 2)
lc1d_kernel(const float* __restrict__ x,
            const float* __restrict__ wgt,
            const float* __restrict__ bias,
            float* __restrict__ out)
{
    extern __shared__ float smem[];
    const unsigned sb = smem_u32(smem);

    const int tid  = threadIdx.x;
    const int lane = tid & 31;            // local l index (compute)
    const int warp = tid >> 5;
    const int bp0  = (warp & 3) * 4;      // b-pair group start (compute)
    const int og   = (warp >> 2) * 8;     // o group start (compute)
    // o-major raster: 8 co-resident o-blocks share each x l-window via L2
    const int o0   = blockIdx.x * O_TILE;
    const int l0   = blockIdx.y * L_TILE;

    // ============ fill state (warp-specialized, fully hoisted) ============
    // X warps (0-3): warp = ci. 32 b-rows, lanes sweep w=0..31 (coalesced
    //   128B) + 2 tail elements/thread (w=32,33).
    // W warps (4-7): warp-4 = ci. 16 oi-rows, lanes 0..23 sweep the
    //   96-float run as float4 (coalesced 384B).
    const bool is_x = (warp < 4);
    const float* srcA;
    const float* srcB = nullptr;
    unsigned dstA, dstB = 0;
    long cadv;
    if (is_x) {
        const int ci0 = warp;
        srcA = x + (long)ci0 * WIN + l0 + lane;             // b=0 row
        dstA = (unsigned)(ci0 * 16 * 68 + lane * 2);
        srcB = x + ((long)((lane >> 1) * CIN + ci0)) * WIN + l0 + 32 + (lane & 1);
        dstB = (unsigned)(((ci0 * 16 + (lane >> 2)) * 34
                           + 32 + (lane & 1)) * 2 + ((lane >> 1) & 1));
        cadv = (long)CC * WIN;
    } else {
        const int ci0 = warp - 4;
        srcA = wgt + ((long)(o0 * CIN + ci0)) * (LOUT * KW) + l0 * KW + lane * 4;
        dstA = (unsigned)(STAGE_X + ci0 * 16 * 96 + lane * 4);
        cadv = (long)CC * LOUT * KW;
    }

    u64 acc[4][8];
    #pragma unroll
    for (int p = 0; p < 4; p++)
        #pragma unroll
        for (int o = 0; o < 8; o++) acc[p][o] = 0ull;

    #define ISSUE(buf) do {                                                 \
        unsigned d0_ = sb + (unsigned)(buf) * STAGE_BYTES + dstA * 4u;      \
        if (is_x) {                                                         \
            _Pragma("unroll")                                               \
            for (int i_ = 0; i_ < 32; i_++)    /* b = i_, all 32 rows */    \
                cpa4(d0_ + (unsigned)(((i_ >> 1) * 68 + (i_ & 1)) * 4),     \
                     srcA + (long)i_ * (CIN * WIN));                        \
            unsigned dB_ = sb + (unsigned)(buf) * STAGE_BYTES + dstB * 4u;  \
            cpa4(dB_, srcB);                           /* b = lane>>1 */    \
            cpa4(dB_ + 8u * 68u * 4u,                  /* b += 16 */        \
                 srcB + (long)16 * (CIN * WIN));                            \
            srcB += cadv;                                                   \
        } else if (lane < 24) {                                             \
            _Pragma("unroll")                                               \
            for (int i_ = 0; i_ < 16; i_++)    /* oi = i_ */                \
                cpa16(d0_ + (unsigned)(i_ * 96 * 4),                        \
                      srcA + (long)i_ * (CIN * LOUT * KW));                 \
        }                                                                   \
        srcA += cadv;                                                       \
    } while (0)

    // prologue: prefetch stage 0
    ISSUE(0); CP_COMMIT();

    #pragma unroll 1
    for (int s = 0; s < NST; s++) {
        CP_WAIT0();                        // stage s's fills complete
        __syncthreads();                   // visible block-wide; buf s-1 free

        if (s + 1 < NST) {                 // fill s+1; overlaps compute(s)
            ISSUE((s + 1) & 1);
            CP_COMMIT();
        }

        const float* Xb = smem + (s & 1) * STAGE_F;
        const float* Wb = Xb + STAGE_X;
        const u64* Xu = reinterpret_cast<const u64*>(Xb);

        #pragma unroll
        for (int ci = 0; ci < CC; ci++) {
            #pragma unroll
            for (int k = 0; k < KW; k++) {
                const u64* xp = Xu + (ci * 16 + bp0) * XPAD + lane + k;
                const u64 px0 = xp[0];
                const u64 px1 = xp[XPAD];
                const u64 px2 = xp[2 * XPAD];
                const u64 px3 = xp[3 * XPAD];
                // stride-3 lane addressing: coprime with 32 banks
                const float* wp = Wb + (ci * O_TILE + og) * 96 + lane * KW + k;
                #pragma unroll
                for (int oi = 0; oi < 8; oi++) {
                    u64 wv = pack_dup(wp[oi * 96]);
                    ffma2(acc[0][oi], px0, wv);
                    ffma2(acc[1][oi], px1, wv);
                    ffma2(acc[2][oi], px2, wv);
                    ffma2(acc[3][oi], px3, wv);
                }
            }
        }
    }

    // epilogue: bias + coalesced stores (l-contiguous)
    const int b0 = (warp & 3) * 8;
    #pragma unroll
    for (int oi = 0; oi < 8; oi++) {
        int o = o0 + og + oi;
        float bv = bias[o * LOUT + l0 + lane];
        #pragma unroll
        for (int p = 0; p < 4; p++) {
            float f0, f1;
            unpack2(acc[p][oi], f0, f1);
            int b = b0 + 2 * p;
            out[(b * COUT + o) * LOUT + l0 + lane]       = f0 + bv;
            out[((b + 1) * COUT + o) * LOUT + l0 + lane] = f1 + bv;
        }
    }
}

extern "C" void kernel_launch(void* const* d_in, const int* in_sizes, int n_in,
                              void* d_out, int out_size)
{
    const float* x    = (const float*)d_in[0];
    const float* wgt  = (const float*)d_in[1];
    const float* bias = (const float*)d_in[2];
    float* out        = (float*)d_out;

    cudaFuncSetAttribute(lc1d_kernel,
                         cudaFuncAttributeMaxDynamicSharedMemorySize, SMEM_BYTES);

    dim3 grid(COUT / O_TILE, LOUT / L_TILE);   // (8, 64): o fastest
    lc1d_kernel<<<grid, NTHREADS, SMEM_BYTES>>>(x, wgt, bias, out);
}

// round 11
// speedup vs baseline: 1.2309x; 1.1198x over previous
#include <cuda_runtime.h>

// LocallyConnected1d: out[b,o,l] = sum_{c,k} x[b,c,l+k]*w[o,c,l,k] + bias[o,l]
// B=32, Cin=128, Cout=128, L=2048, K=3, S=1, W=2050, fp32.
//
// R11: pre-transpose x -> g_xp[c][w][b] so the X smem fill is 9x cp.async.16
// per warp-stage (was 34x 4B LDGSTS = the measured L1 parasite). X smem rows
// are 128B with chunk swizzle (c ^= w&7): compute reads 2x LDS.128 per
// (ci,k), conflict-free, no padding. W path / pipeline / epilogue = R10.

#define CIN     128
#define COUT    128
#define LOUT    2048
#define KW      3
#define WIN     2050

#define L_TILE  32
#define O_TILE  16
#define CC      4                     // Cin per pipeline stage
#define NST     (CIN / CC)            // 32 stages
#define NTHREADS 256

#define STAGE_X (CC * 34 * 32)        // 4352 floats ([ci][w][32b], swizzled)
#define STAGE_W (CC * O_TILE * 96)    // 6144 floats
#define STAGE_F (STAGE_X + STAGE_W)   // 10496 floats
#define STAGE_BYTES (STAGE_F * 4)     // 41984 B
#define SMEM_BYTES (2 * STAGE_BYTES)  // 83968 B -> 2 blocks/SM

typedef unsigned long long u64;

// x transposed to [c][w][b]: fill reads become 128B-contiguous rows.
__device__ float g_xp[CIN * WIN * 32];

static __device__ __forceinline__ u64 pack_dup(float a) {
    u64 r; asm("mov.b64 %0, {%1, %1};" : "=l"(r) : "f"(a)); return r;
}
static __device__ __forceinline__ void unpack2(u64 v, float& a, float& b) {
    asm("mov.b64 {%0, %1}, %2;" : "=f"(a), "=f"(b) : "l"(v));
}
static __device__ __forceinline__ void ffma2(u64& d, u64 a, u64 b) {
    asm("fma.rn.f32x2 %0, %1, %2, %0;" : "+l"(d) : "l"(a), "l"(b));
}
static __device__ __forceinline__ unsigned smem_u32(const void* p) {
    unsigned r;
    asm("{ .reg .u64 t; cvta.to.shared.u64 t, %1; cvt.u32.u64 %0, t; }"
        : "=r"(r) : "l"(p));
    return r;
}
static __device__ __forceinline__ void cpa16(unsigned d, const float* s) {
    asm volatile("cp.async.cg.shared.global [%0], [%1], 16;" :: "r"(d), "l"(s));
}
static __device__ __forceinline__ void cpa16p(unsigned d, const float* s, bool p) {
    if (p) cpa16(d, s);
}
#define CP_COMMIT() asm volatile("cp.async.commit_group;" ::: "memory")
#define CP_WAIT0()  asm volatile("cp.async.wait_group 0;" ::: "memory")

// ---------------- pre-pass: x[b][c][w] -> g_xp[c][w][b] -------------------
__global__ void __launch_bounds__(256, 4)
transpose_x_kernel(const float* __restrict__ x)
{
    __shared__ float t[32][33];
    const int c  = blockIdx.y;
    const int w0 = blockIdx.x * 32;
    const int tx = threadIdx.x & 31;
    const int ty = threadIdx.x >> 5;

    #pragma unroll
    for (int i = 0; i < 4; i++) {            // read coalesced over w
        int b = ty + i * 8;
        int w = w0 + tx;
        t[b][tx] = (w < WIN) ? x[((long)b * CIN + c) * WIN + w] : 0.f;
    }
    __syncthreads();
    #pragma unroll
    for (int i = 0; i < 4; i++) {            // write coalesced over b
        int w = w0 + ty + i * 8;
        if (w < WIN)
            g_xp[((long)c * WIN + w) * 32 + tx] = t[tx][ty + i * 8];
    }
}

// ------------------------------- main --------------------------------------
__global__ void __launch_bounds__(NTHREADS, 2)
lc1d_kernel(const float* __restrict__ wgt,
            const float* __restrict__ bias,
            float* __restrict__ out)
{
    extern __shared__ float smem[];
    const unsigned sb = smem_u32(smem);

    const int tid  = threadIdx.x;
    const int lane = tid & 31;            // local l index (compute)
    const int warp = tid >> 5;
    const int bp0  = (warp & 3) * 4;      // b-pair group start (compute)
    const int og   = (warp >> 2) * 8;     // o group start (compute)
    const int o0   = blockIdx.x * O_TILE; // o-major raster (x L2 reuse)
    const int l0   = blockIdx.y * L_TILE;

    // ============ fill state (warp-specialized, fully hoisted) ============
    // X warps (0-3): warp = ci. Row (ci,w) = 128B = 8 chunks of 16B.
    //   op i: lane -> (w = i*4 + lane>>3, chunk = lane&7); 512B contiguous
    //   global per op; dst chunk swizzled by w&7. 8 full ops + 1 half op
    //   (w=32,33, lanes 0..15).
    // W warps (4-7): warp-4 = ci, 16 oi-rows, lanes 0..23 sweep 96 floats.
    const bool is_x = (warp < 4);
    const float* srcA;
    unsigned dstE = 0, dstO = 0, dstW = 0;
    long cadv;
    const int hi = lane >> 3, lo8 = lane & 7;
    if (is_x) {
        const int ci0 = warp;
        srcA = g_xp + ((long)(ci0 * WIN) + l0 + hi) * 32 + lo8 * 4;
        // even i: chunk = lo8 ^ hi ; odd i: chunk = lo8 ^ (hi+4)
        dstE = (unsigned)((ci0 * 34 + hi) * 32 + (lo8 ^ hi) * 4);
        dstO = (unsigned)((ci0 * 34 + hi) * 32 + (lo8 ^ (hi + 4)) * 4);
        cadv = (long)CC * WIN * 32;
    } else {
        const int ci0 = warp - 4;
        srcA = wgt + ((long)(o0 * CIN + ci0)) * (LOUT * KW) + l0 * KW + lane * 4;
        dstW = (unsigned)(STAGE_X + ci0 * 16 * 96 + lane * 4);
        cadv = (long)CC * LOUT * KW;
    }

    u64 acc[4][8];
    #pragma unroll
    for (int p = 0; p < 4; p++)
        #pragma unroll
        for (int o = 0; o < 8; o++) acc[p][o] = 0ull;

    #define ISSUE(buf) do {                                                 \
        if (is_x) {                                                         \
            unsigned dE_ = sb + (unsigned)(buf) * STAGE_BYTES + dstE * 4u;  \
            unsigned dO_ = sb + (unsigned)(buf) * STAGE_BYTES + dstO * 4u;  \
            _Pragma("unroll")                                               \
            for (int i_ = 0; i_ < 8; i_++) {   /* w = i_*4 + hi */          \
                unsigned d_ = ((i_ & 1) ? dO_ : dE_) + (unsigned)(i_ * 512);\
                cpa16(d_, srcA + (long)i_ * 128);                           \
            }                                                               \
            cpa16p(dE_ + 8u * 512u, srcA + 8L * 128, lane < 16);            \
        } else {                                                            \
            unsigned dW_ = sb + (unsigned)(buf) * STAGE_BYTES + dstW * 4u;  \
            if (lane < 24) {                                                \
                _Pragma("unroll")                                           \
                for (int i_ = 0; i_ < 16; i_++)   /* oi = i_ */             \
                    cpa16(dW_ + (unsigned)(i_ * 96 * 4),                    \
                          srcA + (long)i_ * (CIN * LOUT * KW));             \
            }                                                               \
        }                                                                   \
        srcA += cadv;                                                       \
    } while (0)

    // prologue: prefetch stage 0
    ISSUE(0); CP_COMMIT();

    const int C0 = bp0 >> 1;              // logical 16B chunk of bp0,bp0+1
    #pragma unroll 1
    for (int s = 0; s < NST; s++) {
        CP_WAIT0();                        // stage s's fills complete
        __syncthreads();                   // visible block-wide; buf s-1 free

        if (s + 1 < NST) {                 // fill s+1; overlaps compute(s)
            ISSUE((s + 1) & 1);
            CP_COMMIT();
        }

        const float* Xb = smem + (s & 1) * STAGE_F;
        const float* Wb = Xb + STAGE_X;
        const float4* X4 = reinterpret_cast<const float4*>(Xb);

        #pragma unroll
        for (int ci = 0; ci < CC; ci++) {
            #pragma unroll
            for (int k = 0; k < KW; k++) {
                const int w   = lane + k;
                const int w7  = w & 7;
                const int rb  = (ci * 34 + w) * 8;
                // 2x LDS.128: chunks C0, C0+1 (swizzled); phases of 8
                // consecutive lanes hit 8 distinct chunks -> conflict-free
                ulonglong2 va = *reinterpret_cast<const ulonglong2*>(
                                    X4 + rb + (C0 ^ w7));
                ulonglong2 vb = *reinterpret_cast<const ulonglong2*>(
                                    X4 + rb + ((C0 + 1) ^ w7));
                // w: stride-3 lane addressing, coprime with 32 banks
                const float* wp = Wb + (ci * O_TILE + og) * 96 + lane * KW + k;
                #pragma unroll
                for (int oi = 0; oi < 8; oi++) {
                    u64 wv = pack_dup(wp[oi * 96]);
                    ffma2(acc[0][oi], va.x, wv);
                    ffma2(acc[1][oi], va.y, wv);
                    ffma2(acc[2][oi], vb.x, wv);
                    ffma2(acc[3][oi], vb.y, wv);
                }
            }
        }
    }

    // epilogue: bias + coalesced stores (l-contiguous)
    const int b0 = (warp & 3) * 8;
    #pragma unroll
    for (int oi = 0; oi < 8; oi++) {
        int o = o0 + og + oi;
        float bv = bias[o * LOUT + l0 + lane];
        #pragma unroll
        for (int p = 0; p < 4; p++) {
            float f0, f1;
            unpack2(acc[p][oi], f0, f1);
            int b = b0 + 2 * p;
            out[(b * COUT + o) * LOUT + l0 + lane]       = f0 + bv;
            out[((b + 1) * COUT + o) * LOUT + l0 + lane] = f1 + bv;
        }
    }
}

extern "C" void kernel_launch(void* const* d_in, const int* in_sizes, int n_in,
                              void* d_out, int out_size)
{
    const float* x    = (const float*)d_in[0];
    const float* wgt  = (const float*)d_in[1];
    const float* bias = (const float*)d_in[2];
    float* out        = (float*)d_out;

    cudaFuncSetAttribute(lc1d_kernel,
                         cudaFuncAttributeMaxDynamicSharedMemorySize, SMEM_BYTES);

    dim3 tgrid((WIN + 31) / 32, CIN);          // (65, 128)
    transpose_x_kernel<<<tgrid, 256>>>(x);

    dim3 grid(COUT / O_TILE, LOUT / L_TILE);   // (8, 64): o fastest
    lc1d_kernel<<<grid, NTHREADS, SMEM_BYTES>>>(wgt, bias, out);
}

// round 12
// speedup vs baseline: 1.2545x; 1.0192x over previous
#include <cuda_runtime.h>

// LocallyConnected1d: out[b,o,l] = sum_{c,k} x[b,c,l+k]*w[o,c,l,k] + bias[o,l]
// B=32, Cin=128, Cout=128, L=2048, K=3, S=1, W=2050, fp32.
//
// R11 structure (pre-transposed x, 16B cp.async fills, chunk-swizzled X
// smem, f32x2 packed FMA) + R12: all 6 x LDS.128 hoisted per ci so the
// LDS latency is paid once per ci and the FFMA stream overlaps it.

#define CIN     128
#define COUT    128
#define LOUT    2048
#define KW      3
#define WIN     2050

#define L_TILE  32
#define O_TILE  16
#define CC      4                     // Cin per pipeline stage
#define NST     (CIN / CC)            // 32 stages
#define NTHREADS 256

#define STAGE_X (CC * 34 * 32)        // 4352 floats ([ci][w][32b], swizzled)
#define STAGE_W (CC * O_TILE * 96)    // 6144 floats
#define STAGE_F (STAGE_X + STAGE_W)   // 10496 floats
#define STAGE_BYTES (STAGE_F * 4)     // 41984 B
#define SMEM_BYTES (2 * STAGE_BYTES)  // 83968 B -> 2 blocks/SM

typedef unsigned long long u64;

// x transposed to [c][w][b]: fill reads become 128B-contiguous rows.
__device__ float g_xp[CIN * WIN * 32];

static __device__ __forceinline__ u64 pack_dup(float a) {
    u64 r; asm("mov.b64 %0, {%1, %1};" : "=l"(r) : "f"(a)); return r;
}
static __device__ __forceinline__ void unpack2(u64 v, float& a, float& b) {
    asm("mov.b64 {%0, %1}, %2;" : "=f"(a), "=f"(b) : "l"(v));
}
static __device__ __forceinline__ void ffma2(u64& d, u64 a, u64 b) {
    asm("fma.rn.f32x2 %0, %1, %2, %0;" : "+l"(d) : "l"(a), "l"(b));
}
static __device__ __forceinline__ unsigned smem_u32(const void* p) {
    unsigned r;
    asm("{ .reg .u64 t; cvta.to.shared.u64 t, %1; cvt.u32.u64 %0, t; }"
        : "=r"(r) : "l"(p));
    return r;
}
static __device__ __forceinline__ void cpa16(unsigned d, const float* s) {
    asm volatile("cp.async.cg.shared.global [%0], [%1], 16;" :: "r"(d), "l"(s));
}
static __device__ __forceinline__ void cpa16p(unsigned d, const float* s, bool p) {
    if (p) cpa16(d, s);
}
#define CP_COMMIT() asm volatile("cp.async.commit_group;" ::: "memory")
#define CP_WAIT0()  asm volatile("cp.async.wait_group 0;" ::: "memory")

// ---------------- pre-pass: x[b][c][w] -> g_xp[c][w][b] -------------------
__global__ void __launch_bounds__(256, 4)
transpose_x_kernel(const float* __restrict__ x)
{
    __shared__ float t[32][33];
    const int c  = blockIdx.y;
    const int w0 = blockIdx.x * 32;
    const int tx = threadIdx.x & 31;
    const int ty = threadIdx.x >> 5;

    #pragma unroll
    for (int i = 0; i < 4; i++) {            // read coalesced over w
        int b = ty + i * 8;
        int w = w0 + tx;
        t[b][tx] = (w < WIN) ? x[((long)b * CIN + c) * WIN + w] : 0.f;
    }
    __syncthreads();
    #pragma unroll
    for (int i = 0; i < 4; i++) {            // write coalesced over b
        int w = w0 + ty + i * 8;
        if (w < WIN)
            g_xp[((long)c * WIN + w) * 32 + tx] = t[tx][ty + i * 8];
    }
}

// ------------------------------- main --------------------------------------
__global__ void __launch_bounds__(NTHREADS, 2)
lc1d_kernel(const float* __restrict__ wgt,
            const float* __restrict__ bias,
            float* __restrict__ out)
{
    extern __shared__ float smem[];
    const unsigned sb = smem_u32(smem);

    const int tid  = threadIdx.x;
    const int lane = tid & 31;            // local l index (compute)
    const int warp = tid >> 5;
    const int bp0  = (warp & 3) * 4;      // b-pair group start (compute)
    const int og   = (warp >> 2) * 8;     // o group start (compute)
    const int o0   = blockIdx.x * O_TILE; // o-major raster (x L2 reuse)
    const int l0   = blockIdx.y * L_TILE;

    // ============ fill state (warp-specialized, fully hoisted) ============
    // X warps (0-3): warp = ci. Row (ci,w) = 128B = 8 chunks of 16B.
    //   op i: lane -> (w = i*4 + lane>>3, chunk = lane&7); 512B contiguous
    //   global per op; dst chunk swizzled by w&7. 8 full ops + 1 half op.
    // W warps (4-7): warp-4 = ci, 16 oi-rows, lanes 0..23 sweep 96 floats.
    const bool is_x = (warp < 4);
    const float* srcA;
    unsigned dstE = 0, dstO = 0, dstW = 0;
    long cadv;
    const int hi = lane >> 3, lo8 = lane & 7;
    if (is_x) {
        const int ci0 = warp;
        srcA = g_xp + ((long)(ci0 * WIN) + l0 + hi) * 32 + lo8 * 4;
        dstE = (unsigned)((ci0 * 34 + hi) * 32 + (lo8 ^ hi) * 4);
        dstO = (unsigned)((ci0 * 34 + hi) * 32 + (lo8 ^ (hi + 4)) * 4);
        cadv = (long)CC * WIN * 32;
    } else {
        const int ci0 = warp - 4;
        srcA = wgt + ((long)(o0 * CIN + ci0)) * (LOUT * KW) + l0 * KW + lane * 4;
        dstW = (unsigned)(STAGE_X + ci0 * 16 * 96 + lane * 4);
        cadv = (long)CC * LOUT * KW;
    }

    u64 acc[4][8];
    #pragma unroll
    for (int p = 0; p < 4; p++)
        #pragma unroll
        for (int o = 0; o < 8; o++) acc[p][o] = 0ull;

    #define ISSUE(buf) do {                                                 \
        if (is_x) {                                                         \
            unsigned dE_ = sb + (unsigned)(buf) * STAGE_BYTES + dstE * 4u;  \
            unsigned dO_ = sb + (unsigned)(buf) * STAGE_BYTES + dstO * 4u;  \
            _Pragma("unroll")                                               \
            for (int i_ = 0; i_ < 8; i_++) {   /* w = i_*4 + hi */          \
                unsigned d_ = ((i_ & 1) ? dO_ : dE_) + (unsigned)(i_ * 512);\
                cpa16(d_, srcA + (long)i_ * 128);                           \
            }                                                               \
            cpa16p(dE_ + 8u * 512u, srcA + 8L * 128, lane < 16);            \
        } else {                                                            \
            unsigned dW_ = sb + (unsigned)(buf) * STAGE_BYTES + dstW * 4u;  \
            if (lane < 24) {                                                \
                _Pragma("unroll")                                           \
                for (int i_ = 0; i_ < 16; i_++)   /* oi = i_ */             \
                    cpa16(dW_ + (unsigned)(i_ * 96 * 4),                    \
                          srcA + (long)i_ * (CIN * LOUT * KW));             \
            }                                                               \
        }                                                                   \
        srcA += cadv;                                                       \
    } while (0)

    // prologue: prefetch stage 0
    ISSUE(0); CP_COMMIT();

    const int C0 = bp0 >> 1;              // logical 16B chunk of bp0,bp0+1
    #pragma unroll 1
    for (int s = 0; s < NST; s++) {
        CP_WAIT0();                        // stage s's fills complete
        __syncthreads();                   // visible block-wide; buf s-1 free

        if (s + 1 < NST) {                 // fill s+1; overlaps compute(s)
            ISSUE((s + 1) & 1);
            CP_COMMIT();
        }

        const float* Xb = smem + (s & 1) * STAGE_F;
        const float* Wb = Xb + STAGE_X;
        const float4* X4 = reinterpret_cast<const float4*>(Xb);

        #pragma unroll
        for (int ci = 0; ci < CC; ci++) {
            // hoist all 6 x LDS.128 for this ci: independent loads issued
            // back-to-back; FFMA stream below overlaps their latency
            ulonglong2 va[KW], vb[KW];
            #pragma unroll
            for (int k = 0; k < KW; k++) {
                const int w  = lane + k;
                const int w7 = w & 7;
                const int rb = (ci * 34 + w) * 8;
                va[k] = *reinterpret_cast<const ulonglong2*>(
                            X4 + rb + (C0 ^ w7));
                vb[k] = *reinterpret_cast<const ulonglong2*>(
                            X4 + rb + ((C0 + 1) ^ w7));
            }
            #pragma unroll
            for (int k = 0; k < KW; k++) {
                // w: stride-3 lane addressing, coprime with 32 banks
                const float* wp = Wb + (ci * O_TILE + og) * 96 + lane * KW + k;
                #pragma unroll
                for (int oi = 0; oi < 8; oi++) {
                    u64 wv = pack_dup(wp[oi * 96]);
                    ffma2(acc[0][oi], va[k].x, wv);
                    ffma2(acc[1][oi], va[k].y, wv);
                    ffma2(acc[2][oi], vb[k].x, wv);
                    ffma2(acc[3][oi], vb[k].y, wv);
                }
            }
        }
    }

    // epilogue: bias + coalesced stores (l-contiguous)
    const int b0 = (warp & 3) * 8;
    #pragma unroll
    for (int oi = 0; oi < 8; oi++) {
        int o = o0 + og + oi;
        float bv = bias[o * LOUT + l0 + lane];
        #pragma unroll
        for (int p = 0; p < 4; p++) {
            float f0, f1;
            unpack2(acc[p][oi], f0, f1);
            int b = b0 + 2 * p;
            out[(b * COUT + o) * LOUT + l0 + lane]       = f0 + bv;
            out[((b + 1) * COUT + o) * LOUT + l0 + lane] = f1 + bv;
        }
    }
}

extern "C" void kernel_launch(void* const* d_in, const int* in_sizes, int n_in,
                              void* d_out, int out_size)
{
    const float* x    = (const float*)d_in[0];
    const float* wgt  = (const float*)d_in[1];
    const float* bias = (const float*)d_in[2];
    float* out        = (float*)d_out;

    cudaFuncSetAttribute(lc1d_kernel,
                         cudaFuncAttributeMaxDynamicSharedMemorySize, SMEM_BYTES);

    dim3 tgrid((WIN + 31) / 32, CIN);          // (65, 128)
    transpose_x_kernel<<<tgrid, 256>>>(x);

    dim3 grid(COUT / O_TILE, LOUT / L_TILE);   // (8, 64): o fastest
    lc1d_kernel<<<grid, NTHREADS, SMEM_BYTES>>>(wgt, bias, out);
}